// round 1
// baseline (speedup 1.0000x reference)
#include <cuda_runtime.h>
#include <math.h>

#define N_NODES 8192
#define EMB     128
#define KL      3
#define NKE     (KL * EMB)   // 384

// ---------------- scratch (no allocations allowed) ----------------
__device__ float g_Wp [ (size_t)N_NODES * NKE ];   // [N, 3*128]
__device__ float g_Wq [ (size_t)N_NODES * NKE ];   // [N, 3*128]
__device__ float g_dec[ (size_t)N_NODES * EMB ];   // [N, 128]
__device__ float g_Dout[N_NODES];
__device__ float g_Din [N_NODES];

// ---------------- degree kernels ----------------
__global__ void zero_dout_kernel() {
    int i = blockIdx.x * blockDim.x + threadIdx.x;
    if (i < N_NODES) g_Dout[i] = 0.0f;
}

// D_out[j] = sum_i A[i,j]  (column sums), split over rows with atomics
__global__ void colsum_kernel(const float* __restrict__ A) {
    int j = blockIdx.x * blockDim.x + threadIdx.x;
    int chunk = N_NODES / gridDim.y;
    int i0 = blockIdx.y * chunk;
    float s0 = 0.f, s1 = 0.f, s2 = 0.f, s3 = 0.f;
    for (int i = i0; i < i0 + chunk; i += 4) {
        s0 += A[(size_t)(i + 0) * N_NODES + j];
        s1 += A[(size_t)(i + 1) * N_NODES + j];
        s2 += A[(size_t)(i + 2) * N_NODES + j];
        s3 += A[(size_t)(i + 3) * N_NODES + j];
    }
    atomicAdd(&g_Dout[j], (s0 + s1) + (s2 + s3));
}

// D_in[i] = sum_j A[i,j]  (row sums), one warp per row
__global__ void rowsum_kernel(const float* __restrict__ A) {
    int row  = blockIdx.x * (blockDim.x >> 5) + (threadIdx.x >> 5);
    int lane = threadIdx.x & 31;
    const float4* Ar = (const float4*)(A + (size_t)row * N_NODES);
    float s = 0.f;
    for (int i = lane; i < N_NODES / 4; i += 32) {
        float4 v = Ar[i];
        s += (v.x + v.y) + (v.z + v.w);
    }
    #pragma unroll
    for (int o = 16; o; o >>= 1) s += __shfl_xor_sync(0xFFFFFFFFu, s, o);
    if (lane == 0) g_Din[row] = s;
}

// ---------------- generic tiled SGEMM ----------------
// C(m,n) = sum_k A(k,m) * B(k,n)
//   A element address: A[k*SAK + m*SAM]   (exactly one of SAK/SAM is 1)
//   B element address: B[k*SBK + n*SBN]
// EPI: 0 = +bias[n], store C[m*ldc+n]        (projection / Wp,Wq)
//      1 = v/deg[m], leaky_relu, store [K,N,D] remap  (p_k / q_k)
//      2 = +bias[n], store C[m*EMB+n]        (dec)
//      3 = v * a*d^b*exp(c*d) with d=dist[m,n], store C[m*N+n]  (e_ij)
template<int SAK, int SAM, int SBK, int SBN, int EPI>
__global__ void __launch_bounds__(256)
gemm_kernel(const float* __restrict__ A, const float* __restrict__ B,
            float* __restrict__ C, int Kdim, int ldc,
            const float* __restrict__ bias,
            const float* __restrict__ deg,
            const float* __restrict__ dist,
            const float* __restrict__ sa,
            const float* __restrict__ sb,
            const float* __restrict__ sc)
{
    constexpr int BM = 64, BN = 64, BK = 16;
    __shared__ float As[BK][BM + 4];
    __shared__ float Bs[BK][BN + 4];

    const int t  = threadIdx.x;
    const int tx = t & 15;        // n-dir
    const int ty = t >> 4;        // m-dir
    const int m0 = blockIdx.y * BM;
    const int n0 = blockIdx.x * BN;

    float acc[4][4];
    #pragma unroll
    for (int i = 0; i < 4; i++)
        #pragma unroll
        for (int j = 0; j < 4; j++) acc[i][j] = 0.f;

    for (int k0 = 0; k0 < Kdim; k0 += BK) {
        // ---- load A tile ----
        if (SAM == 1) {
            const int kk = t >> 4, mm = (t & 15) << 2;
            *(float4*)&As[kk][mm] =
                *(const float4*)&A[(size_t)(k0 + kk) * SAK + (m0 + mm)];
        } else { // SAK == 1
            const int mm = t >> 2, kk = (t & 3) << 2;
            float4 v = *(const float4*)&A[(size_t)(m0 + mm) * SAM + (k0 + kk)];
            As[kk + 0][mm] = v.x; As[kk + 1][mm] = v.y;
            As[kk + 2][mm] = v.z; As[kk + 3][mm] = v.w;
        }
        // ---- load B tile ----
        if (SBN == 1) {
            const int kk = t >> 4, nn = (t & 15) << 2;
            *(float4*)&Bs[kk][nn] =
                *(const float4*)&B[(size_t)(k0 + kk) * SBK + (n0 + nn)];
        } else { // SBK == 1
            const int nn = t >> 2, kk = (t & 3) << 2;
            float4 v = *(const float4*)&B[(size_t)(n0 + nn) * SBN + (k0 + kk)];
            Bs[kk + 0][nn] = v.x; Bs[kk + 1][nn] = v.y;
            Bs[kk + 2][nn] = v.z; Bs[kk + 3][nn] = v.w;
        }
        __syncthreads();

        #pragma unroll
        for (int kk = 0; kk < BK; kk++) {
            float4 av = *(const float4*)&As[kk][ty << 2];
            float4 bv = *(const float4*)&Bs[kk][tx << 2];
            float a4[4] = {av.x, av.y, av.z, av.w};
            float b4[4] = {bv.x, bv.y, bv.z, bv.w};
            #pragma unroll
            for (int i = 0; i < 4; i++)
                #pragma unroll
                for (int j = 0; j < 4; j++)
                    acc[i][j] += a4[i] * b4[j];
        }
        __syncthreads();
    }

    // ---- epilogue ----
    float sa0 = 0.f, sb0 = 0.f, sc0 = 0.f;
    if (EPI == 3) { sa0 = *sa; sb0 = *sb; sc0 = *sc; }

    #pragma unroll
    for (int i = 0; i < 4; i++) {
        const int m = m0 + (ty << 2) + i;
        const int n = n0 + (tx << 2);
        float degm = 0.f;
        if (EPI == 1) degm = deg[m];

        float r[4];
        float4 dv;
        if (EPI == 3) dv = *(const float4*)&dist[(size_t)m * N_NODES + n];
        const float dl[4] = { (EPI==3)?dv.x:0.f, (EPI==3)?dv.y:0.f,
                              (EPI==3)?dv.z:0.f, (EPI==3)?dv.w:0.f };

        #pragma unroll
        for (int j = 0; j < 4; j++) {
            float v = acc[i][j];
            if (EPI == 0 || EPI == 2) v += bias[n + j];
            if (EPI == 1) {
                v = v / degm;
                v = (v > 0.f) ? v : 0.01f * v;
            }
            if (EPI == 3) {
                float d  = dl[j];
                float fx = sa0 * powf(d, sb0) * expf(sc0 * d);
                v = v * fx;
            }
            r[j] = v;
        }
        float4 rv = make_float4(r[0], r[1], r[2], r[3]);

        if (EPI == 0) {
            *(float4*)&C[(size_t)m * ldc + n] = rv;
        } else if (EPI == 2) {
            *(float4*)&C[(size_t)m * EMB + n] = rv;
        } else if (EPI == 1) {
            // n = k*128 + e ; out layout [K, N, D]
            size_t off = (size_t)(n >> 7) * ((size_t)N_NODES * EMB)
                       + (size_t)m * EMB + (n & 127);
            *(float4*)&C[off] = rv;
        } else { // EPI == 3
            *(float4*)&C[(size_t)m * N_NODES + n] = rv;
        }
    }
}

// ---------------- launcher ----------------
extern "C" void kernel_launch(void* const* d_in, const int* in_sizes, int n_in,
                              void* d_out, int out_size)
{
    const float* p    = (const float*)d_in[0];
    const float* q    = (const float*)d_in[1];
    const float* A    = (const float*)d_in[2];
    const float* dist = (const float*)d_in[3];
    const float* Ws   = (const float*)d_in[4];
    const float* bs   = (const float*)d_in[5];
    const float* Wd   = (const float*)d_in[6];
    const float* bd   = (const float*)d_in[7];
    const float* a    = (const float*)d_in[8];
    const float* b    = (const float*)d_in[9];
    const float* c    = (const float*)d_in[10];

    float* out   = (float*)d_out;
    float* out_p = out;
    float* out_q = out   + (size_t)KL * N_NODES * EMB;
    float* out_e = out_q + (size_t)KL * N_NODES * EMB;

    float *wp, *wq, *dec, *dout, *din;
    cudaGetSymbolAddress((void**)&wp,   g_Wp);
    cudaGetSymbolAddress((void**)&wq,   g_Wq);
    cudaGetSymbolAddress((void**)&dec,  g_dec);
    cudaGetSymbolAddress((void**)&dout, g_Dout);
    cudaGetSymbolAddress((void**)&din,  g_Din);

    // degrees
    zero_dout_kernel<<<N_NODES / 256, 256>>>();
    colsum_kernel<<<dim3(N_NODES / 256, 8), 256>>>(A);
    rowsum_kernel<<<N_NODES / 8, 256>>>(A);

    // per-layer linear projections of ORIGINAL inputs, fused across K:
    // g_Wp[n, k*128+e] = sum_d p[n,d]*Ws[k,e,d] + bs[k,e]
    gemm_kernel<1, EMB, 1, EMB, 0>
        <<<dim3(NKE / 64, N_NODES / 64), 256>>>(p, Ws, wp, EMB, NKE,
                                                bs, nullptr, nullptr,
                                                nullptr, nullptr, nullptr);
    gemm_kernel<1, EMB, 1, EMB, 0>
        <<<dim3(NKE / 64, N_NODES / 64), 256>>>(q, Ws, wq, EMB, NKE,
                                                bs, nullptr, nullptr,
                                                nullptr, nullptr, nullptr);

    // p_k = leaky_relu( (A^T @ Wp) / D_out[j] ) -> out_p  [K,N,D]
    gemm_kernel<N_NODES, 1, NKE, 1, 1>
        <<<dim3(NKE / 64, N_NODES / 64), 256>>>(A, wp, out_p, N_NODES, 0,
                                                nullptr, dout, nullptr,
                                                nullptr, nullptr, nullptr);
    // q_k = leaky_relu( (A @ Wq) / D_in[j] ) -> out_q  [K,N,D]
    gemm_kernel<1, N_NODES, NKE, 1, 1>
        <<<dim3(NKE / 64, N_NODES / 64), 256>>>(A, wq, out_q, N_NODES, 0,
                                                nullptr, din, nullptr,
                                                nullptr, nullptr, nullptr);

    // dec = p_k[-1] @ Wd^T + bd
    const float* pk2 = out_p + (size_t)(KL - 1) * N_NODES * EMB;
    gemm_kernel<1, EMB, 1, EMB, 2>
        <<<dim3(EMB / 64, N_NODES / 64), 256>>>(pk2, Wd, dec, EMB, EMB,
                                                bd, nullptr, nullptr,
                                                nullptr, nullptr, nullptr);

    // e_ij = (dec @ q_k[-1]^T) * a * d^b * exp(c*d)
    const float* qk2 = out_q + (size_t)(KL - 1) * N_NODES * EMB;
    gemm_kernel<1, EMB, 1, EMB, 3>
        <<<dim3(N_NODES / 64, N_NODES / 64), 256>>>(dec, qk2, out_e, EMB, 0,
                                                    nullptr, nullptr, dist,
                                                    a, b, c);
}

// round 2
// speedup vs baseline: 1.0071x; 1.0071x over previous
#include <cuda_runtime.h>
#include <math.h>

#define N_NODES 8192
#define EMB     128
#define KL      3
#define NKE     (KL * EMB)   // 384

// ---------------- scratch (no allocations allowed) ----------------
__device__ float g_Wp [ (size_t)N_NODES * NKE ];   // [N, 3*128]
__device__ float g_Wq [ (size_t)N_NODES * NKE ];   // [N, 3*128]
__device__ float g_dec[ (size_t)N_NODES * EMB ];   // [N, 128]
__device__ float g_Dout[N_NODES];
__device__ float g_Din [N_NODES];

// ---------------- degree kernels ----------------
__global__ void zero_dout_kernel() {
    int i = blockIdx.x * blockDim.x + threadIdx.x;
    if (i < N_NODES) g_Dout[i] = 0.0f;
}

// D_out[j] = sum_i A[i,j]  (column sums), split over rows with atomics
__global__ void colsum_kernel(const float* __restrict__ A) {
    int j = blockIdx.x * blockDim.x + threadIdx.x;
    int chunk = N_NODES / gridDim.y;
    int i0 = blockIdx.y * chunk;
    float s0 = 0.f, s1 = 0.f, s2 = 0.f, s3 = 0.f;
    for (int i = i0; i < i0 + chunk; i += 4) {
        s0 += A[(size_t)(i + 0) * N_NODES + j];
        s1 += A[(size_t)(i + 1) * N_NODES + j];
        s2 += A[(size_t)(i + 2) * N_NODES + j];
        s3 += A[(size_t)(i + 3) * N_NODES + j];
    }
    atomicAdd(&g_Dout[j], (s0 + s1) + (s2 + s3));
}

// D_in[i] = sum_j A[i,j]  (row sums), one warp per row
__global__ void rowsum_kernel(const float* __restrict__ A) {
    int row  = blockIdx.x * (blockDim.x >> 5) + (threadIdx.x >> 5);
    int lane = threadIdx.x & 31;
    const float4* Ar = (const float4*)(A + (size_t)row * N_NODES);
    float s = 0.f;
    for (int i = lane; i < N_NODES / 4; i += 32) {
        float4 v = Ar[i];
        s += (v.x + v.y) + (v.z + v.w);
    }
    #pragma unroll
    for (int o = 16; o; o >>= 1) s += __shfl_xor_sync(0xFFFFFFFFu, s, o);
    if (lane == 0) g_Din[row] = s;
}

// ---------------- generic tiled SGEMM ----------------
// C(m,n) = sum_k A(k,m) * B(k,n)
//   A element address: A[k*SAK + m*SAM]   (exactly one of SAK/SAM is 1)
//   B element address: B[k*SBK + n*SBN]
// EPI: 0 = +bias[n], store C[m*ldc+n]        (projection / Wp,Wq)
//      1 = v/deg[m], leaky_relu, store [K,N,D] remap  (p_k / q_k)
//      2 = +bias[n], store C[m*EMB+n]        (dec)
//      3 = v * a*d^b*exp(c*d) with d=dist[m,n], store C[m*N+n]  (e_ij)
template<int SAK, int SAM, int SBK, int SBN, int EPI>
__global__ void __launch_bounds__(256)
gemm_kernel(const float* __restrict__ A, const float* __restrict__ B,
            float* __restrict__ C, int Kdim, int ldc,
            const float* __restrict__ bias,
            const float* __restrict__ deg,
            const float* __restrict__ dist,
            const float* __restrict__ sa,
            const float* __restrict__ sb,
            const float* __restrict__ sc)
{
    constexpr int BM = 64, BN = 64, BK = 16;
    __shared__ float As[BK][BM + 4];
    __shared__ float Bs[BK][BN + 4];

    const int t  = threadIdx.x;
    const int tx = t & 15;        // n-dir
    const int ty = t >> 4;        // m-dir
    const int m0 = blockIdx.y * BM;
    const int n0 = blockIdx.x * BN;

    float acc[4][4];
    #pragma unroll
    for (int i = 0; i < 4; i++)
        #pragma unroll
        for (int j = 0; j < 4; j++) acc[i][j] = 0.f;

    for (int k0 = 0; k0 < Kdim; k0 += BK) {
        // ---- load A tile ----
        if (SAM == 1) {
            const int kk = t >> 4, mm = (t & 15) << 2;
            *(float4*)&As[kk][mm] =
                *(const float4*)&A[(size_t)(k0 + kk) * SAK + (m0 + mm)];
        } else { // SAK == 1
            const int mm = t >> 2, kk = (t & 3) << 2;
            float4 v = *(const float4*)&A[(size_t)(m0 + mm) * SAM + (k0 + kk)];
            As[kk + 0][mm] = v.x; As[kk + 1][mm] = v.y;
            As[kk + 2][mm] = v.z; As[kk + 3][mm] = v.w;
        }
        // ---- load B tile ----
        if (SBN == 1) {
            const int kk = t >> 4, nn = (t & 15) << 2;
            *(float4*)&Bs[kk][nn] =
                *(const float4*)&B[(size_t)(k0 + kk) * SBK + (n0 + nn)];
        } else { // SBK == 1
            const int nn = t >> 2, kk = (t & 3) << 2;
            float4 v = *(const float4*)&B[(size_t)(n0 + nn) * SBN + (k0 + kk)];
            Bs[kk + 0][nn] = v.x; Bs[kk + 1][nn] = v.y;
            Bs[kk + 2][nn] = v.z; Bs[kk + 3][nn] = v.w;
        }
        __syncthreads();

        #pragma unroll
        for (int kk = 0; kk < BK; kk++) {
            float4 av = *(const float4*)&As[kk][ty << 2];
            float4 bv = *(const float4*)&Bs[kk][tx << 2];
            float a4[4] = {av.x, av.y, av.z, av.w};
            float b4[4] = {bv.x, bv.y, bv.z, bv.w};
            #pragma unroll
            for (int i = 0; i < 4; i++)
                #pragma unroll
                for (int j = 0; j < 4; j++)
                    acc[i][j] += a4[i] * b4[j];
        }
        __syncthreads();
    }

    // ---- epilogue ----
    float sa0 = 0.f, sb0 = 0.f, sc0 = 0.f;
    if (EPI == 3) { sa0 = *sa; sb0 = *sb; sc0 = *sc; }

    #pragma unroll
    for (int i = 0; i < 4; i++) {
        const int m = m0 + (ty << 2) + i;
        const int n = n0 + (tx << 2);
        float degm = 0.f;
        if (EPI == 1) degm = deg[m];

        float r[4];
        float4 dv;
        if (EPI == 3) dv = *(const float4*)&dist[(size_t)m * N_NODES + n];
        const float dl[4] = { (EPI==3)?dv.x:0.f, (EPI==3)?dv.y:0.f,
                              (EPI==3)?dv.z:0.f, (EPI==3)?dv.w:0.f };

        #pragma unroll
        for (int j = 0; j < 4; j++) {
            float v = acc[i][j];
            if (EPI == 0 || EPI == 2) v += bias[n + j];
            if (EPI == 1) {
                v = v / degm;
                v = (v > 0.f) ? v : 0.01f * v;
            }
            if (EPI == 3) {
                float d  = dl[j];
                float fx = sa0 * powf(d, sb0) * expf(sc0 * d);
                v = v * fx;
            }
            r[j] = v;
        }
        float4 rv = make_float4(r[0], r[1], r[2], r[3]);

        if (EPI == 0) {
            *(float4*)&C[(size_t)m * ldc + n] = rv;
        } else if (EPI == 2) {
            *(float4*)&C[(size_t)m * EMB + n] = rv;
        } else if (EPI == 1) {
            // n = k*128 + e ; out layout [K, N, D]
            size_t off = (size_t)(n >> 7) * ((size_t)N_NODES * EMB)
                       + (size_t)m * EMB + (n & 127);
            *(float4*)&C[off] = rv;
        } else { // EPI == 3
            *(float4*)&C[(size_t)m * N_NODES + n] = rv;
        }
    }
}

// ---------------- launcher ----------------
extern "C" void kernel_launch(void* const* d_in, const int* in_sizes, int n_in,
                              void* d_out, int out_size)
{
    const float* p    = (const float*)d_in[0];
    const float* q    = (const float*)d_in[1];
    const float* A    = (const float*)d_in[2];
    const float* dist = (const float*)d_in[3];
    const float* Ws   = (const float*)d_in[4];
    const float* bs   = (const float*)d_in[5];
    const float* Wd   = (const float*)d_in[6];
    const float* bd   = (const float*)d_in[7];
    const float* a    = (const float*)d_in[8];
    const float* b    = (const float*)d_in[9];
    const float* c    = (const float*)d_in[10];

    float* out   = (float*)d_out;
    float* out_p = out;
    float* out_q = out   + (size_t)KL * N_NODES * EMB;
    float* out_e = out_q + (size_t)KL * N_NODES * EMB;

    float *wp, *wq, *dec, *dout, *din;
    cudaGetSymbolAddress((void**)&wp,   g_Wp);
    cudaGetSymbolAddress((void**)&wq,   g_Wq);
    cudaGetSymbolAddress((void**)&dec,  g_dec);
    cudaGetSymbolAddress((void**)&dout, g_Dout);
    cudaGetSymbolAddress((void**)&din,  g_Din);

    // degrees
    zero_dout_kernel<<<N_NODES / 256, 256>>>();
    colsum_kernel<<<dim3(N_NODES / 256, 8), 256>>>(A);
    rowsum_kernel<<<N_NODES / 8, 256>>>(A);

    // per-layer linear projections of ORIGINAL inputs, fused across K:
    // g_Wp[n, k*128+e] = sum_d p[n,d]*Ws[k,e,d] + bs[k,e]
    gemm_kernel<1, EMB, 1, EMB, 0>
        <<<dim3(NKE / 64, N_NODES / 64), 256>>>(p, Ws, wp, EMB, NKE,
                                                bs, nullptr, nullptr,
                                                nullptr, nullptr, nullptr);
    gemm_kernel<1, EMB, 1, EMB, 0>
        <<<dim3(NKE / 64, N_NODES / 64), 256>>>(q, Ws, wq, EMB, NKE,
                                                bs, nullptr, nullptr,
                                                nullptr, nullptr, nullptr);

    // p_k = leaky_relu( (A^T @ Wp) / D_out[j] ) -> out_p  [K,N,D]
    gemm_kernel<N_NODES, 1, NKE, 1, 1>
        <<<dim3(NKE / 64, N_NODES / 64), 256>>>(A, wp, out_p, N_NODES, 0,
                                                nullptr, dout, nullptr,
                                                nullptr, nullptr, nullptr);
    // q_k = leaky_relu( (A @ Wq) / D_in[j] ) -> out_q  [K,N,D]
    gemm_kernel<1, N_NODES, NKE, 1, 1>
        <<<dim3(NKE / 64, N_NODES / 64), 256>>>(A, wq, out_q, N_NODES, 0,
                                                nullptr, din, nullptr,
                                                nullptr, nullptr, nullptr);

    // dec = p_k[-1] @ Wd^T + bd
    const float* pk2 = out_p + (size_t)(KL - 1) * N_NODES * EMB;
    gemm_kernel<1, EMB, 1, EMB, 2>
        <<<dim3(EMB / 64, N_NODES / 64), 256>>>(pk2, Wd, dec, EMB, EMB,
                                                bd, nullptr, nullptr,
                                                nullptr, nullptr, nullptr);

    // e_ij = (dec @ q_k[-1]^T) * a * d^b * exp(c*d)
    const float* qk2 = out_q + (size_t)(KL - 1) * N_NODES * EMB;
    gemm_kernel<1, EMB, 1, EMB, 3>
        <<<dim3(N_NODES / 64, N_NODES / 64), 256>>>(dec, qk2, out_e, EMB, 0,
                                                    nullptr, nullptr, dist,
                                                    a, b, c);
}